// round 7
// baseline (speedup 1.0000x reference)
#include <cuda_runtime.h>
#include <cstdint>
#include <cstddef>

// ---------------------------------------------------------------------------
// MiniMaxExperts: grouped SwiGLU FFN, sm_103 via compute_103-portable ISA.
//   (harness compiles arch=compute_103 virtual -> NO tcgen05/TMA "a"-features;
//    use mma.sync.m16n8k8.tf32 + cp.async + cvt.rna.tf32)
//   out = (silu(x@w1[e]) * (x@w3[e])) @ w2[e], ragged expert groups.
// E=8, H=1024, I=2816, T=4096, group sizes all multiples of 128.
// ---------------------------------------------------------------------------

#define DI __device__ __forceinline__

static constexpr int TT = 4096;
static constexpr int HH = 1024;
static constexpr int II = 2816;
static constexpr int EE = 8;
static constexpr int TM = 128;    // CTA token tile
static constexpr int TN = 128;    // CTA out-feature tile
static constexpr int KC = 32;     // K chunk per stage

static constexpr int AS_STRIDE = 36;    // padded floats per A row (conflict-free frags)
static constexpr int BS_STRIDE = 132;   // padded floats per B row
static constexpr int A_FL = TM * AS_STRIDE;   // 4608 floats
static constexpr int B_FL = KC * BS_STRIDE;   // 4224 floats

// fp32 scratch for SwiGLU intermediate h[T, I] (46 MB)
__device__ float g_h[(size_t)TT * II];

// ---- PTX helpers -----------------------------------------------------------

DI uint32_t smem_u32(const void* p) {
    uint32_t a;
    asm("{ .reg .u64 t; cvta.to.shared.u64 t, %1; cvt.u32.u64 %0, t; }"
        : "=r"(a) : "l"(p));
    return a;
}

DI uint32_t f2tf(float f) {  // fp32 -> tf32, round-to-nearest (kills truncation bias)
    uint32_t r;
    asm("cvt.rna.tf32.f32 %0, %1;" : "=r"(r) : "f"(f));
    return r;
}

DI void cp16(uint32_t dst, const float* src) {
    asm volatile("cp.async.cg.shared.global [%0], [%1], 16;"
                 :: "r"(dst), "l"(src));
}
#define CP_COMMIT() asm volatile("cp.async.commit_group;" ::: "memory")
#define CP_WAIT0()  asm volatile("cp.async.wait_group 0;" ::: "memory")

// D += A*B, m16n8k8 tf32 (row.col), fp32 accumulate
DI void mma8(float* d, const uint32_t* a, const uint32_t* b) {
    asm volatile(
        "mma.sync.aligned.m16n8k8.row.col.f32.tf32.tf32.f32 "
        "{%0,%1,%2,%3}, {%4,%5,%6,%7}, {%8,%9}, {%0,%1,%2,%3};"
        : "+f"(d[0]), "+f"(d[1]), "+f"(d[2]), "+f"(d[3])
        : "r"(a[0]), "r"(a[1]), "r"(a[2]), "r"(a[3]), "r"(b[0]), "r"(b[1]));
}

DI int tile_expert(const int* __restrict__ gs, int m0) {
    int e = 0, cum = 0;
#pragma unroll
    for (int i = 0; i < EE; i++) {
        int s = __ldg(gs + i);
        if (m0 >= cum + s) e = i + 1;
        cum += s;
    }
    return e;
}

// ---- stage loaders (cp.async, 256 threads) ---------------------------------

// A tile: 128 rows x 32 K (fp32, row stride lda). 1024 x 16B chunks.
DI void load_A(float* s, const float* __restrict__ A, int lda, int k0, int tid) {
#pragma unroll
    for (int it = 0; it < 4; it++) {
        int id = tid + it * 256;
        int row = id >> 3, k4 = id & 7;
        cp16(smem_u32(s + row * AS_STRIDE + k4 * 4),
             A + (size_t)row * lda + k0 + k4 * 4);
    }
}
// B tile: 32 K-rows x 128 n (fp32, row stride ldb; base already at n0).
DI void load_B(float* s, const float* __restrict__ B, int ldb, int k0, int tid) {
#pragma unroll
    for (int it = 0; it < 4; it++) {
        int id = tid + it * 256;
        int row = id >> 5, n4 = id & 31;
        cp16(smem_u32(s + row * BS_STRIDE + n4 * 4),
             B + (size_t)(k0 + row) * ldb + n4 * 4);
    }
}

// ---- fragment loads (conflict-free padded SMEM) ----------------------------

DI void frag_A(uint32_t* af, const float* As, int mbase, int k, int lane) {
    const int r = lane >> 2, c4 = lane & 3;
    const float* p = As + (mbase + r) * AS_STRIDE + k + c4;
    af[0] = f2tf(p[0]);
    af[1] = f2tf(p[8 * AS_STRIDE]);
    af[2] = f2tf(p[4]);
    af[3] = f2tf(p[8 * AS_STRIDE + 4]);
}
DI void frag_B(uint32_t* bf, const float* Bs, int nbase, int k, int lane) {
    const int r = lane >> 2, c4 = lane & 3;
    const float* p = Bs + (k + c4) * BS_STRIDE + nbase + r;
    bf[0] = f2tf(p[0]);
    bf[1] = f2tf(p[4 * BS_STRIDE]);
}

// ---- stage A: h = silu(x@w1) * (x@w3) --------------------------------------

static constexpr int UP_STAGE_FL = A_FL + 2 * B_FL;              // 13056 floats
static constexpr uint32_t UP_SMEM = 2 * UP_STAGE_FL * 4;         // 104448 B

__global__ void __launch_bounds__(256, 1) moe_up_kernel(
    const float* __restrict__ x, const int* __restrict__ gs,
    const float* __restrict__ w1, const float* __restrict__ w3) {
    extern __shared__ __align__(16) float smem[];
    const int tid = threadIdx.x;
    const int lane = tid & 31, warp = tid >> 5;
    const int wm = warp >> 2, wn = warp & 3;   // 2 x 4 warp grid (m64 x n32)
    const int m0 = blockIdx.x * TM;            // m fastest: same-B CTAs adjacent
    const int n0 = blockIdx.y * TN;

    const int e = tile_expert(gs, m0);
    const float* A  = x + (size_t)m0 * HH;
    const float* B1 = w1 + (size_t)e * HH * II + n0;
    const float* B3 = w3 + (size_t)e * HH * II + n0;

    float accU[4][4][4], accG[4][4][4];
#pragma unroll
    for (int mt = 0; mt < 4; mt++)
#pragma unroll
        for (int nt = 0; nt < 4; nt++)
#pragma unroll
            for (int i = 0; i < 4; i++) { accU[mt][nt][i] = 0.f; accG[mt][nt][i] = 0.f; }

    // prologue
    load_A(smem, A, HH, 0, tid);
    load_B(smem + A_FL, B1, II, 0, tid);
    load_B(smem + A_FL + B_FL, B3, II, 0, tid);
    CP_COMMIT();
    CP_WAIT0();
    __syncthreads();

    const int NC = HH / KC;  // 32
#pragma unroll 1
    for (int c = 0; c < NC; c++) {
        float* cur = smem + (c & 1) * UP_STAGE_FL;
        if (c + 1 < NC) {
            float* nxt = smem + ((c + 1) & 1) * UP_STAGE_FL;
            const int k0 = (c + 1) * KC;
            load_A(nxt, A, HH, k0, tid);
            load_B(nxt + A_FL, B1, II, k0, tid);
            load_B(nxt + A_FL + B_FL, B3, II, k0, tid);
            CP_COMMIT();
        }
        const float* As  = cur;
        const float* B1s = cur + A_FL;
        const float* B3s = cur + A_FL + B_FL;
#pragma unroll
        for (int ks = 0; ks < 4; ks++) {
            const int k = ks * 8;
            uint32_t af[4][4], b1f[4][2], b3f[4][2];
#pragma unroll
            for (int mt = 0; mt < 4; mt++)
                frag_A(af[mt], As, wm * 64 + mt * 16, k, lane);
#pragma unroll
            for (int nt = 0; nt < 4; nt++) {
                frag_B(b1f[nt], B1s, wn * 32 + nt * 8, k, lane);
                frag_B(b3f[nt], B3s, wn * 32 + nt * 8, k, lane);
            }
#pragma unroll
            for (int mt = 0; mt < 4; mt++)
#pragma unroll
                for (int nt = 0; nt < 4; nt++) {
                    mma8(accU[mt][nt], af[mt], b1f[nt]);
                    mma8(accG[mt][nt], af[mt], b3f[nt]);
                }
        }
        if (c + 1 < NC) { CP_WAIT0(); __syncthreads(); }
    }

    // epilogue: SwiGLU in registers, float2 stores (fragment coords identical)
    float* ho = g_h + (size_t)m0 * II + n0;
    const int r = lane >> 2, c4 = lane & 3;
#pragma unroll
    for (int mt = 0; mt < 4; mt++) {
#pragma unroll
        for (int nt = 0; nt < 4; nt++) {
            const int row = wm * 64 + mt * 16 + r;
            const int col = wn * 32 + nt * 8 + c4 * 2;
            const float* u = accU[mt][nt];
            const float* g = accG[mt][nt];
            float2 v0, v1;
            v0.x = (u[0] / (1.f + __expf(-u[0]))) * g[0];
            v0.y = (u[1] / (1.f + __expf(-u[1]))) * g[1];
            v1.x = (u[2] / (1.f + __expf(-u[2]))) * g[2];
            v1.y = (u[3] / (1.f + __expf(-u[3]))) * g[3];
            *(float2*)(ho + (size_t)row * II + col) = v0;
            *(float2*)(ho + (size_t)(row + 8) * II + col) = v1;
        }
    }
}

// ---- stage B: out = h @ w2 -------------------------------------------------

static constexpr int DN_STAGE_FL = A_FL + B_FL;                  // 8832 floats
static constexpr uint32_t DN_SMEM = 2 * DN_STAGE_FL * 4;         // 70656 B

__global__ void __launch_bounds__(256, 2) moe_down_kernel(
    const int* __restrict__ gs, const float* __restrict__ w2,
    float* __restrict__ out) {
    extern __shared__ __align__(16) float smem[];
    const int tid = threadIdx.x;
    const int lane = tid & 31, warp = tid >> 5;
    const int wm = warp >> 2, wn = warp & 3;
    const int m0 = blockIdx.x * TM;
    const int n0 = blockIdx.y * TN;

    const int e = tile_expert(gs, m0);
    const float* A = g_h + (size_t)m0 * II;
    const float* B = w2 + (size_t)e * II * HH + n0;

    float acc[4][4][4];
#pragma unroll
    for (int mt = 0; mt < 4; mt++)
#pragma unroll
        for (int nt = 0; nt < 4; nt++)
#pragma unroll
            for (int i = 0; i < 4; i++) acc[mt][nt][i] = 0.f;

    load_A(smem, A, II, 0, tid);
    load_B(smem + A_FL, B, HH, 0, tid);
    CP_COMMIT();
    CP_WAIT0();
    __syncthreads();

    const int NC = II / KC;  // 88
#pragma unroll 1
    for (int c = 0; c < NC; c++) {
        float* cur = smem + (c & 1) * DN_STAGE_FL;
        if (c + 1 < NC) {
            float* nxt = smem + ((c + 1) & 1) * DN_STAGE_FL;
            const int k0 = (c + 1) * KC;
            load_A(nxt, A, II, k0, tid);
            load_B(nxt + A_FL, B, HH, k0, tid);
            CP_COMMIT();
        }
        const float* As = cur;
        const float* Bs = cur + A_FL;
#pragma unroll
        for (int ks = 0; ks < 4; ks++) {
            const int k = ks * 8;
            uint32_t af[4][4], bf[4][2];
#pragma unroll
            for (int mt = 0; mt < 4; mt++)
                frag_A(af[mt], As, wm * 64 + mt * 16, k, lane);
#pragma unroll
            for (int nt = 0; nt < 4; nt++)
                frag_B(bf[nt], Bs, wn * 32 + nt * 8, k, lane);
#pragma unroll
            for (int mt = 0; mt < 4; mt++)
#pragma unroll
                for (int nt = 0; nt < 4; nt++)
                    mma8(acc[mt][nt], af[mt], bf[nt]);
        }
        if (c + 1 < NC) { CP_WAIT0(); __syncthreads(); }
    }

    float* oo = out + (size_t)m0 * HH + n0;
    const int r = lane >> 2, c4 = lane & 3;
#pragma unroll
    for (int mt = 0; mt < 4; mt++) {
#pragma unroll
        for (int nt = 0; nt < 4; nt++) {
            const int row = wm * 64 + mt * 16 + r;
            const int col = wn * 32 + nt * 8 + c4 * 2;
            const float* d = acc[mt][nt];
            *(float2*)(oo + (size_t)row * HH + col) = make_float2(d[0], d[1]);
            *(float2*)(oo + (size_t)(row + 8) * HH + col) = make_float2(d[2], d[3]);
        }
    }
}

// ---- launch ----------------------------------------------------------------

extern "C" void kernel_launch(void* const* d_in, const int* in_sizes, int n_in,
                              void* d_out, int out_size) {
    const float* x  = (const float*)d_in[0];
    const int*   gs = (const int*)d_in[1];
    const float* w1 = (const float*)d_in[2];
    const float* w2 = (const float*)d_in[3];
    const float* w3 = (const float*)d_in[4];
    float* out = (float*)d_out;

    cudaFuncSetAttribute(moe_up_kernel,
                         cudaFuncAttributeMaxDynamicSharedMemorySize, UP_SMEM);
    cudaFuncSetAttribute(moe_down_kernel,
                         cudaFuncAttributeMaxDynamicSharedMemorySize, DN_SMEM);

    cudaFuncSetAttribute(moe_up_kernel,
                         cudaFuncAttributePreferredSharedMemoryCarveout, 100);
    cudaFuncSetAttribute(moe_down_kernel,
                         cudaFuncAttributePreferredSharedMemoryCarveout, 100);

    // m-tile fastest (blockIdx.x) so CTAs sharing a weight slice are adjacent
    moe_up_kernel<<<dim3(TT / TM, II / TN), 256, UP_SMEM>>>(x, gs, w1, w3);
    moe_down_kernel<<<dim3(TT / TM, HH / TN), 256, DN_SMEM>>>(gs, w2, out);
}

// round 11
// speedup vs baseline: 1.0244x; 1.0244x over previous
#include <cuda_runtime.h>
#include <cstdint>
#include <cstddef>

// ---------------------------------------------------------------------------
// MiniMaxExperts: grouped SwiGLU FFN, sm_103 via compute_103-portable ISA.
//   mma.sync.m16n8k8.tf32 + cp.async (3-stage) + cvt.rna.tf32
//   out = (silu(x@w1[e]) * (x@w3[e])) @ w2[e], ragged expert groups.
// R8: up kernel TN=64 @ 2 CTAs/SM (16 warps), 3-stage pipelines both kernels.
// ---------------------------------------------------------------------------

#define DI __device__ __forceinline__

static constexpr int TT = 4096;
static constexpr int HH = 1024;
static constexpr int II = 2816;
static constexpr int EE = 8;
static constexpr int TM = 128;     // CTA token tile
static constexpr int KC = 32;      // K chunk per stage

static constexpr int AS_STRIDE = 36;     // padded floats per A row
static constexpr int A_FL = TM * AS_STRIDE;        // 4608 floats

// up kernel: TN=64
static constexpr int TNU = 64;
static constexpr int BSU_STRIDE = 68;
static constexpr int BU_FL = KC * BSU_STRIDE;      // 2176 floats
static constexpr int UP_STAGE_FL = A_FL + 2 * BU_FL;   // 8960
static constexpr uint32_t UP_SMEM = 3 * UP_STAGE_FL * 4;   // 107520 B

// down kernel: TN=128
static constexpr int TND = 128;
static constexpr int BSD_STRIDE = 132;
static constexpr int BD_FL = KC * BSD_STRIDE;      // 4224 floats
static constexpr int DN_STAGE_FL = A_FL + BD_FL;   // 8832
static constexpr uint32_t DN_SMEM = 3 * DN_STAGE_FL * 4;   // 105984 B

// fp32 scratch for SwiGLU intermediate h[T, I] (46 MB)
__device__ float g_h[(size_t)TT * II];

// ---- PTX helpers -----------------------------------------------------------

DI uint32_t smem_u32(const void* p) {
    uint32_t a;
    asm("{ .reg .u64 t; cvta.to.shared.u64 t, %1; cvt.u32.u64 %0, t; }"
        : "=r"(a) : "l"(p));
    return a;
}

DI uint32_t f2tf(float f) {  // fp32 -> tf32 round-to-nearest
    uint32_t r;
    asm("cvt.rna.tf32.f32 %0, %1;" : "=r"(r) : "f"(f));
    return r;
}

DI void cp16(uint32_t dst, const float* src) {
    asm volatile("cp.async.cg.shared.global [%0], [%1], 16;"
                 :: "r"(dst), "l"(src));
}
#define CP_COMMIT() asm volatile("cp.async.commit_group;" ::: "memory")
#define CP_WAIT0()  asm volatile("cp.async.wait_group 0;" ::: "memory")
#define CP_WAIT1()  asm volatile("cp.async.wait_group 1;" ::: "memory")

// D += A*B, m16n8k8 tf32 (row.col), fp32 accumulate
DI void mma8(float* d, const uint32_t* a, const uint32_t* b) {
    asm volatile(
        "mma.sync.aligned.m16n8k8.row.col.f32.tf32.tf32.f32 "
        "{%0,%1,%2,%3}, {%4,%5,%6,%7}, {%8,%9}, {%0,%1,%2,%3};"
        : "+f"(d[0]), "+f"(d[1]), "+f"(d[2]), "+f"(d[3])
        : "r"(a[0]), "r"(a[1]), "r"(a[2]), "r"(a[3]), "r"(b[0]), "r"(b[1]));
}

DI int tile_expert(const int* __restrict__ gs, int m0) {
    int e = 0, cum = 0;
#pragma unroll
    for (int i = 0; i < EE; i++) {
        int s = __ldg(gs + i);
        if (m0 >= cum + s) e = i + 1;
        cum += s;
    }
    return e;
}

// ---- stage loaders (cp.async, 256 threads) ---------------------------------

// A tile: 128 rows x 32 K. 1024 16B chunks.
DI void load_A(float* s, const float* __restrict__ A, int lda, int k0, int tid) {
#pragma unroll
    for (int it = 0; it < 4; it++) {
        int id = tid + it * 256;
        int row = id >> 3, k4 = id & 7;
        cp16(smem_u32(s + row * AS_STRIDE + k4 * 4),
             A + (size_t)row * lda + k0 + k4 * 4);
    }
}
// B tile, 128-wide n: 32 K-rows x 128 n. 1024 chunks.
DI void load_B128(float* s, const float* __restrict__ B, int ldb, int k0, int tid) {
#pragma unroll
    for (int it = 0; it < 4; it++) {
        int id = tid + it * 256;
        int row = id >> 5, n4 = id & 31;
        cp16(smem_u32(s + row * BSD_STRIDE + n4 * 4),
             B + (size_t)(k0 + row) * ldb + n4 * 4);
    }
}
// B tile, 64-wide n: 32 K-rows x 64 n. 512 chunks.
DI void load_B64(float* s, const float* __restrict__ B, int ldb, int k0, int tid) {
#pragma unroll
    for (int it = 0; it < 2; it++) {
        int id = tid + it * 256;
        int row = id >> 4, n4 = id & 15;
        cp16(smem_u32(s + row * BSU_STRIDE + n4 * 4),
             B + (size_t)(k0 + row) * ldb + n4 * 4);
    }
}

// ---- fragment loads (conflict-free padded SMEM) ----------------------------

DI void frag_A(uint32_t* af, const float* As, int mbase, int k, int lane) {
    const int r = lane >> 2, c4 = lane & 3;
    const float* p = As + (mbase + r) * AS_STRIDE + k + c4;
    af[0] = f2tf(p[0]);
    af[1] = f2tf(p[8 * AS_STRIDE]);
    af[2] = f2tf(p[4]);
    af[3] = f2tf(p[8 * AS_STRIDE + 4]);
}
DI void frag_B(uint32_t* bf, const float* Bs, int bstride, int nbase, int k, int lane) {
    const int r = lane >> 2, c4 = lane & 3;
    const float* p = Bs + (k + c4) * bstride + nbase + r;
    bf[0] = f2tf(p[0]);
    bf[1] = f2tf(p[4 * bstride]);
}

// ---- stage A: h = silu(x@w1) * (x@w3); TN=64, 2 CTAs/SM --------------------

__global__ void __launch_bounds__(256, 2) moe_up_kernel(
    const float* __restrict__ x, const int* __restrict__ gs,
    const float* __restrict__ w1, const float* __restrict__ w3) {
    extern __shared__ __align__(16) float smem[];
    const int tid = threadIdx.x;
    const int lane = tid & 31, warp = tid >> 5;
    const int wm = warp >> 2, wn = warp & 3;   // 2 x 4 grid of 64x16 warp tiles
    const int m0 = blockIdx.x * TM;
    const int n0 = blockIdx.y * TNU;

    const int e = tile_expert(gs, m0);
    const float* A  = x + (size_t)m0 * HH;
    const float* B1 = w1 + (size_t)e * HH * II + n0;
    const float* B3 = w3 + (size_t)e * HH * II + n0;

    float accU[4][2][4], accG[4][2][4];
#pragma unroll
    for (int mt = 0; mt < 4; mt++)
#pragma unroll
        for (int nt = 0; nt < 2; nt++)
#pragma unroll
            for (int i = 0; i < 4; i++) { accU[mt][nt][i] = 0.f; accG[mt][nt][i] = 0.f; }

    const int NC = HH / KC;  // 32

    // prologue: stage chunks 0 and 1
    {
        float* s0 = smem;
        load_A(s0, A, HH, 0, tid);
        load_B64(s0 + A_FL, B1, II, 0, tid);
        load_B64(s0 + A_FL + BU_FL, B3, II, 0, tid);
        CP_COMMIT();
        float* s1 = smem + UP_STAGE_FL;
        load_A(s1, A, HH, KC, tid);
        load_B64(s1 + A_FL, B1, II, KC, tid);
        load_B64(s1 + A_FL + BU_FL, B3, II, KC, tid);
        CP_COMMIT();
    }

#pragma unroll 1
    for (int c = 0; c < NC; c++) {
        if (c + 1 < NC) { CP_WAIT1(); } else { CP_WAIT0(); }
        __syncthreads();
        if (c + 2 < NC) {
            float* nxt = smem + ((c + 2) % 3) * UP_STAGE_FL;
            const int k0 = (c + 2) * KC;
            load_A(nxt, A, HH, k0, tid);
            load_B64(nxt + A_FL, B1, II, k0, tid);
            load_B64(nxt + A_FL + BU_FL, B3, II, k0, tid);
            CP_COMMIT();
        }
        const float* cur = smem + (c % 3) * UP_STAGE_FL;
        const float* As  = cur;
        const float* B1s = cur + A_FL;
        const float* B3s = cur + A_FL + BU_FL;
#pragma unroll
        for (int ks = 0; ks < 4; ks++) {
            const int k = ks * 8;
            uint32_t af[4][4], b1f[2][2], b3f[2][2];
#pragma unroll
            for (int mt = 0; mt < 4; mt++)
                frag_A(af[mt], As, wm * 64 + mt * 16, k, lane);
#pragma unroll
            for (int nt = 0; nt < 2; nt++) {
                frag_B(b1f[nt], B1s, BSU_STRIDE, wn * 16 + nt * 8, k, lane);
                frag_B(b3f[nt], B3s, BSU_STRIDE, wn * 16 + nt * 8, k, lane);
            }
#pragma unroll
            for (int mt = 0; mt < 4; mt++)
#pragma unroll
                for (int nt = 0; nt < 2; nt++) {
                    mma8(accU[mt][nt], af[mt], b1f[nt]);
                    mma8(accG[mt][nt], af[mt], b3f[nt]);
                }
        }
    }

    // epilogue: SwiGLU in registers, float2 stores
    float* ho = g_h + (size_t)m0 * II + n0;
    const int r = lane >> 2, c4 = lane & 3;
#pragma unroll
    for (int mt = 0; mt < 4; mt++) {
#pragma unroll
        for (int nt = 0; nt < 2; nt++) {
            const int row = wm * 64 + mt * 16 + r;
            const int col = wn * 16 + nt * 8 + c4 * 2;
            const float* u = accU[mt][nt];
            const float* g = accG[mt][nt];
            float2 v0, v1;
            v0.x = (u[0] / (1.f + __expf(-u[0]))) * g[0];
            v0.y = (u[1] / (1.f + __expf(-u[1]))) * g[1];
            v1.x = (u[2] / (1.f + __expf(-u[2]))) * g[2];
            v1.y = (u[3] / (1.f + __expf(-u[3]))) * g[3];
            *(float2*)(ho + (size_t)row * II + col) = v0;
            *(float2*)(ho + (size_t)(row + 8) * II + col) = v1;
        }
    }
}

// ---- stage B: out = h @ w2; TN=128, 2 CTAs/SM ------------------------------

__global__ void __launch_bounds__(256, 2) moe_down_kernel(
    const int* __restrict__ gs, const float* __restrict__ w2,
    float* __restrict__ out) {
    extern __shared__ __align__(16) float smem[];
    const int tid = threadIdx.x;
    const int lane = tid & 31, warp = tid >> 5;
    const int wm = warp >> 2, wn = warp & 3;   // 2 x 4 grid of 64x32 warp tiles
    const int m0 = blockIdx.x * TM;
    const int n0 = blockIdx.y * TND;

    const int e = tile_expert(gs, m0);
    const float* A = g_h + (size_t)m0 * II;
    const float* B = w2 + (size_t)e * II * HH + n0;

    float acc[4][4][4];
#pragma unroll
    for (int mt = 0; mt < 4; mt++)
#pragma unroll
        for (int nt = 0; nt < 4; nt++)
#pragma unroll
            for (int i = 0; i < 4; i++) acc[mt][nt][i] = 0.f;

    const int NC = II / KC;  // 88

    {
        float* s0 = smem;
        load_A(s0, A, II, 0, tid);
        load_B128(s0 + A_FL, B, HH, 0, tid);
        CP_COMMIT();
        float* s1 = smem + DN_STAGE_FL;
        load_A(s1, A, II, KC, tid);
        load_B128(s1 + A_FL, B, HH, KC, tid);
        CP_COMMIT();
    }

#pragma unroll 1
    for (int c = 0; c < NC; c++) {
        if (c + 1 < NC) { CP_WAIT1(); } else { CP_WAIT0(); }
        __syncthreads();
        if (c + 2 < NC) {
            float* nxt = smem + ((c + 2) % 3) * DN_STAGE_FL;
            const int k0 = (c + 2) * KC;
            load_A(nxt, A, II, k0, tid);
            load_B128(nxt + A_FL, B, HH, k0, tid);
            CP_COMMIT();
        }
        const float* cur = smem + (c % 3) * DN_STAGE_FL;
        const float* As = cur;
        const float* Bs = cur + A_FL;
#pragma unroll
        for (int ks = 0; ks < 4; ks++) {
            const int k = ks * 8;
            uint32_t af[4][4], bf[4][2];
#pragma unroll
            for (int mt = 0; mt < 4; mt++)
                frag_A(af[mt], As, wm * 64 + mt * 16, k, lane);
#pragma unroll
            for (int nt = 0; nt < 4; nt++)
                frag_B(bf[nt], Bs, BSD_STRIDE, wn * 32 + nt * 8, k, lane);
#pragma unroll
            for (int mt = 0; mt < 4; mt++)
#pragma unroll
                for (int nt = 0; nt < 4; nt++)
                    mma8(acc[mt][nt], af[mt], bf[nt]);
        }
    }

    float* oo = out + (size_t)m0 * HH + n0;
    const int r = lane >> 2, c4 = lane & 3;
#pragma unroll
    for (int mt = 0; mt < 4; mt++) {
#pragma unroll
        for (int nt = 0; nt < 4; nt++) {
            const int row = wm * 64 + mt * 16 + r;
            const int col = wn * 32 + nt * 8 + c4 * 2;
            const float* d = acc[mt][nt];
            *(float2*)(oo + (size_t)row * HH + col) = make_float2(d[0], d[1]);
            *(float2*)(oo + (size_t)(row + 8) * HH + col) = make_float2(d[2], d[3]);
        }
    }
}

// ---- launch ----------------------------------------------------------------

extern "C" void kernel_launch(void* const* d_in, const int* in_sizes, int n_in,
                              void* d_out, int out_size) {
    const float* x  = (const float*)d_in[0];
    const int*   gs = (const int*)d_in[1];
    const float* w1 = (const float*)d_in[2];
    const float* w2 = (const float*)d_in[3];
    const float* w3 = (const float*)d_in[4];
    float* out = (float*)d_out;

    cudaFuncSetAttribute(moe_up_kernel,
                         cudaFuncAttributeMaxDynamicSharedMemorySize, UP_SMEM);
    cudaFuncSetAttribute(moe_down_kernel,
                         cudaFuncAttributeMaxDynamicSharedMemorySize, DN_SMEM);
    cudaFuncSetAttribute(moe_up_kernel,
                         cudaFuncAttributePreferredSharedMemoryCarveout, 100);
    cudaFuncSetAttribute(moe_down_kernel,
                         cudaFuncAttributePreferredSharedMemoryCarveout, 100);

    // m-tile fastest (blockIdx.x): CTAs sharing a weight slice are adjacent
    moe_up_kernel<<<dim3(TT / TM, II / TNU), 256, UP_SMEM>>>(x, gs, w1, w3);
    moe_down_kernel<<<dim3(TT / TM, HH / TND), 256, DN_SMEM>>>(gs, w2, out);
}